// round 12
// baseline (speedup 1.0000x reference)
#include <cuda_runtime.h>
#include <cuda_fp16.h>
#include <math.h>

// Problem constants (fixed by the dataset)
#define N_NODES       65536
#define N_FEAT        64
#define N_HEADS       4
#define NTYPE         4
#define BATCH_ROWS    131072
#define ENTRIES_TOTAL (BATCH_ROWS * NTYPE)   // 524288
#define DEG           8                      // each node appears exactly 8 times
#define ALPHA         0.2f

// Scratch (allocation-free rule: __device__ globals; zero-init at module load)
__device__ int   g_cnt[N_NODES];
__device__ uint2 g_neigh2[N_NODES * DEG];     // packed: x = n0 | n1<<16, y = n2
__device__ uint2 g_feat_h[N_NODES * 16];      // fp16 feature table, 4 halfs per uint2

#define SCATTER_BLOCKS 2048   // 2048*256 = 524,288 entries (1 thread/entry)
#define CONV_BLOCKS    1024   // 1024*256 threads x 4 float4 each = N_NODES*16

// ---------------------------------------------------------------------------
// Kernel 1 (fused, two independent block ranges; scatter first so its
// latency-bound atomics start immediately):
//   [0, SCATTER_BLOCKS)           : packed degree-8 neighbor triplets
//   [SCATTER_BLOCKS, +CONV_BLOCKS): fp32 -> fp16 feature table,
//                                   4 float4 per thread, 2x STG.128
// g_cnt must be all-zero on entry (static zero-init; gat_kernel re-zeros).
// ---------------------------------------------------------------------------
__global__ void prep_scatter_kernel(const float4* __restrict__ feat4,
                                    const int4*   __restrict__ batch4) {
    if (blockIdx.x < SCATTER_BLOCKS) {
        int idx = blockIdx.x * 256 + threadIdx.x;  // entry
        int r = idx >> 2;                  // batch row
        int i = idx & 3;                   // filter / position of target
        int4 b = batch4[r];                // 4 threads share this line
        int tgt = (i == 0) ? b.x : (i == 1) ? b.y : (i == 2) ? b.z : b.w;
        // cols[i] = all j != i, in order (maps directly to att weight column)
        unsigned n0 = (i == 0) ? b.y : b.x;
        unsigned n1 = (i <= 1) ? b.z : b.y;
        unsigned n2 = (i == 3) ? b.z : b.w;
        int p = atomicAdd(&g_cnt[tgt], 1);
        g_neigh2[tgt * DEG + p] = make_uint2(n0 | (n1 << 16), n2);
    } else {
        int i = (blockIdx.x - SCATTER_BLOCKS) * 256 + threadIdx.x;  // [0, N_NODES*4)
        float4 v0 = feat4[i * 4 + 0];
        float4 v1 = feat4[i * 4 + 1];
        float4 v2 = feat4[i * 4 + 2];
        float4 v3 = feat4[i * 4 + 3];
        __half2 h0 = __floats2half2_rn(v0.x, v0.y);
        __half2 h1 = __floats2half2_rn(v0.z, v0.w);
        __half2 h2 = __floats2half2_rn(v1.x, v1.y);
        __half2 h3 = __floats2half2_rn(v1.z, v1.w);
        __half2 h4 = __floats2half2_rn(v2.x, v2.y);
        __half2 h5 = __floats2half2_rn(v2.z, v2.w);
        __half2 h6 = __floats2half2_rn(v3.x, v3.y);
        __half2 h7 = __floats2half2_rn(v3.z, v3.w);
        uint4 ua, ub;
        ua.x = *reinterpret_cast<unsigned int*>(&h0);
        ua.y = *reinterpret_cast<unsigned int*>(&h1);
        ua.z = *reinterpret_cast<unsigned int*>(&h2);
        ua.w = *reinterpret_cast<unsigned int*>(&h3);
        ub.x = *reinterpret_cast<unsigned int*>(&h4);
        ub.y = *reinterpret_cast<unsigned int*>(&h5);
        ub.z = *reinterpret_cast<unsigned int*>(&h6);
        ub.w = *reinterpret_cast<unsigned int*>(&h7);
        reinterpret_cast<uint4*>(g_feat_h)[i * 2 + 0] = ua;
        reinterpret_cast<uint4*>(g_feat_h)[i * 2 + 1] = ub;
    }
}

// ---------------------------------------------------------------------------
// Kernel 2: per-node reduction (atomic-free), fp16 gathers + HFMA2 math.
//   PDL: weight loads run before cudaGridDependencySynchronize(); everything
//   touching prep outputs (g_feat_h incl. base row, g_neigh2, g_cnt reset)
//   runs after. base is read from the fp16 table (same hot lines as gathers),
//   converted to fp32 for the epilogue.
// ---------------------------------------------------------------------------
__global__ void __launch_bounds__(256, 4) gat_kernel(
    const float*  __restrict__ attw,     // [4 heads][3 positions]
    float4*       __restrict__ out4)     // [N_NODES*64]
{
    int tid = threadIdx.x;
    int t   = blockIdx.x * 16 + (tid >> 4);  // node
    int fc  = tid & 15;                      // half2-pair chunk of the row

    // ---- prep-independent prologue (overlaps prep kernel via PDL) ----
    __half2 w2[12];
#pragma unroll
    for (int k = 0; k < 12; k++) {
        float w = __ldg(attw + k);
        w2[k] = __float2half2_rn(w);
    }

    // ---- wait for prep_scatter_kernel completion ----
    cudaGridDependencySynchronize();

    // base row from the fp16 table (fp32 math in the epilogue)
    uint2 braw = g_feat_h[t * 16 + fc];
    float2 b01 = __half22float2(*reinterpret_cast<__half2*>(&braw.x));
    float2 b23 = __half22float2(*reinterpret_cast<__half2*>(&braw.y));

    // reset counter for next replay (this replay's entries already written)
    if (fc == 0) g_cnt[t] = 0;

    const __half2 NEGINF = __half2half2(__ushort_as_half(0xFC00));
    __half2 acc[8];                          // [head][lo/hi]
#pragma unroll
    for (int k = 0; k < 8; k++) acc[k] = NEGINF;

    const uint2* np = g_neigh2 + t * DEG;

#pragma unroll
    for (int e = 0; e < 8; e++) {
        uint2 pk = np[e];
        int n0 = pk.x & 0xFFFF;
        int n1 = pk.x >> 16;
        int n2 = pk.y;
        uint2 a0 = g_feat_h[n0 * 16 + fc];
        uint2 a1 = g_feat_h[n1 * 16 + fc];
        uint2 a2 = g_feat_h[n2 * 16 + fc];
        __half2 f0l = *reinterpret_cast<__half2*>(&a0.x);
        __half2 f0h = *reinterpret_cast<__half2*>(&a0.y);
        __half2 f1l = *reinterpret_cast<__half2*>(&a1.x);
        __half2 f1h = *reinterpret_cast<__half2*>(&a1.y);
        __half2 f2l = *reinterpret_cast<__half2*>(&a2.x);
        __half2 f2h = *reinterpret_cast<__half2*>(&a2.y);

#pragma unroll
        for (int h = 0; h < 4; h++) {
            __half2 ml = __hmul2(w2[h * 3 + 0], f0l);
            ml = __hfma2(w2[h * 3 + 1], f1l, ml);
            ml = __hfma2(w2[h * 3 + 2], f2l, ml);
            __half2 mh = __hmul2(w2[h * 3 + 0], f0h);
            mh = __hfma2(w2[h * 3 + 1], f1h, mh);
            mh = __hfma2(w2[h * 3 + 2], f2h, mh);
            acc[h * 2 + 0] = __hmax2(acc[h * 2 + 0], ml);
            acc[h * 2 + 1] = __hmax2(acc[h * 2 + 1], mh);
        }
    }

    // out[t, h*64 + f] -> float4 index t*64 + h*16 + fc
    int ob = t * 64 + fc;
#pragma unroll
    for (int h = 0; h < 4; h++) {
        float2 lo = __half22float2(acc[h * 2 + 0]);
        float2 hi = __half22float2(acc[h * 2 + 1]);
        float x0 = b01.x + lo.x;
        float x1 = b01.y + lo.y;
        float x2 = b23.x + hi.x;
        float x3 = b23.y + hi.y;
        out4[ob + h * 16] = make_float4(fmaxf(x0, ALPHA * x0), fmaxf(x1, ALPHA * x1),
                                        fmaxf(x2, ALPHA * x2), fmaxf(x3, ALPHA * x3));
    }
}

// ---------------------------------------------------------------------------
// Launcher: prep on the capture stream, gat launched with the PDL attribute
// so its prologue overlaps prep's tail inside the captured graph.
// ---------------------------------------------------------------------------
extern "C" void kernel_launch(void* const* d_in, const int* in_sizes, int n_in,
                              void* d_out, int out_size) {
    const int*   batch = nullptr;
    const float* feat  = nullptr;
    const float* attw  = nullptr;
    for (int i = 0; i < n_in; i++) {
        if (in_sizes[i] == ENTRIES_TOTAL)              batch = (const int*)d_in[i];
        else if (in_sizes[i] == N_NODES * N_FEAT)      feat  = (const float*)d_in[i];
        else if (in_sizes[i] == N_HEADS * (NTYPE - 1)) attw  = (const float*)d_in[i];
    }

    prep_scatter_kernel<<<SCATTER_BLOCKS + CONV_BLOCKS, 256>>>(
        reinterpret_cast<const float4*>(feat),
        reinterpret_cast<const int4*>(batch));

    cudaLaunchConfig_t cfg = {};
    cfg.gridDim  = dim3(N_NODES / 16, 1, 1);
    cfg.blockDim = dim3(256, 1, 1);
    cfg.dynamicSmemBytes = 0;
    cfg.stream = 0;   // same (legacy) stream the harness captures
    cudaLaunchAttribute attrs[1];
    attrs[0].id = cudaLaunchAttributeProgrammaticStreamSerialization;
    attrs[0].val.programmaticStreamSerializationAllowed = 1;
    cfg.attrs    = attrs;
    cfg.numAttrs = 1;

    cudaLaunchKernelEx(&cfg, gat_kernel,
                       attw,
                       reinterpret_cast<float4*>(d_out));
}

// round 13
// speedup vs baseline: 1.0453x; 1.0453x over previous
#include <cuda_runtime.h>
#include <cuda_fp16.h>
#include <math.h>

// Problem constants (fixed by the dataset)
#define N_NODES       65536
#define N_FEAT        64
#define N_HEADS       4
#define NTYPE         4
#define BATCH_ROWS    131072
#define ENTRIES_TOTAL (BATCH_ROWS * NTYPE)   // 524288
#define DEG           8                      // each node appears exactly 8 times
#define ALPHA         0.2f

// Scratch (allocation-free rule: __device__ globals; zero-init at module load)
__device__ int   g_cnt[N_NODES];
__device__ uint2 g_neigh2[N_NODES * DEG];     // packed: x = n0 | n1<<16, y = n2
__device__ uint2 g_feat_h[N_NODES * 16];      // fp16 feature table, 4 halfs per uint2

#define PREP_BLOCKS 2048   // 2048*256 = 524,288 threads: 1 entry + 2 float4 each

// ---------------------------------------------------------------------------
// Kernel 1: fused per-THREAD prep. Each of the 524,288 threads
//   (a) converts 2 float4 of the feature table to fp16 (one uint4 store),
//   (b) scatters one packed degree-8 neighbor-triplet entry.
// The independent streaming loads of (a) hide the atomic latency of (b),
// and both workloads share all SMs instead of splitting the grid.
// g_cnt must be all-zero on entry (static zero-init; gat_kernel re-zeros).
// ---------------------------------------------------------------------------
__global__ void prep_kernel(const float4* __restrict__ feat4,
                            const int4*   __restrict__ batch4) {
    int idx = blockIdx.x * 256 + threadIdx.x;      // entry id, [0, 524288)

    // ---- (a) convert: feature float4 pair -> 8 halfs ----
    float4 v0 = feat4[idx * 2 + 0];
    float4 v1 = feat4[idx * 2 + 1];

    // ---- (b) scatter: issue batch load early so it overlaps converts ----
    int r = idx >> 2;                  // batch row
    int i = idx & 3;                   // filter / position of target
    int4 b = batch4[r];                // 4 consecutive threads share this line

    __half2 h0 = __floats2half2_rn(v0.x, v0.y);
    __half2 h1 = __floats2half2_rn(v0.z, v0.w);
    __half2 h2 = __floats2half2_rn(v1.x, v1.y);
    __half2 h3 = __floats2half2_rn(v1.z, v1.w);
    uint4 u;
    u.x = *reinterpret_cast<unsigned int*>(&h0);
    u.y = *reinterpret_cast<unsigned int*>(&h1);
    u.z = *reinterpret_cast<unsigned int*>(&h2);
    u.w = *reinterpret_cast<unsigned int*>(&h3);
    reinterpret_cast<uint4*>(g_feat_h)[idx] = u;

    int tgt = (i == 0) ? b.x : (i == 1) ? b.y : (i == 2) ? b.z : b.w;
    // cols[i] = all j != i, in order (maps directly to att weight column)
    unsigned n0 = (i == 0) ? b.y : b.x;
    unsigned n1 = (i <= 1) ? b.z : b.y;
    unsigned n2 = (i == 3) ? b.z : b.w;
    int p = atomicAdd(&g_cnt[tgt], 1);
    g_neigh2[tgt * DEG + p] = make_uint2(n0 | (n1 << 16), n2);
}

// ---------------------------------------------------------------------------
// Kernel 2: per-node reduction (atomic-free), fp16 gathers + HFMA2 math.
//   PDL: the prologue (weights + fp32 base loads, pure-input data) runs
//   BEFORE cudaGridDependencySynchronize(); everything touching prep outputs
//   (g_neigh2, g_feat_h, g_cnt reset) runs after.
//   16 threads/node; gathers are LDG.64 (16 lanes = one 128B line per row).
// ---------------------------------------------------------------------------
__global__ void __launch_bounds__(256, 4) gat_kernel(
    const float4* __restrict__ feat4,    // [N_NODES*16] fp32 (for base)
    const float*  __restrict__ attw,     // [4 heads][3 positions]
    float4*       __restrict__ out4)     // [N_NODES*64]
{
    int tid = threadIdx.x;
    int t   = blockIdx.x * 16 + (tid >> 4);  // node
    int fc  = tid & 15;                      // half2-pair chunk of the row

    // ---- prep-independent prologue (overlaps the prep kernel via PDL) ----
    __half2 w2[12];
#pragma unroll
    for (int k = 0; k < 12; k++) {
        float w = __ldg(attw + k);
        w2[k] = __float2half2_rn(w);
    }
    const float4 base = feat4[t * 16 + fc];

    // ---- wait for prep_kernel completion ----
    cudaGridDependencySynchronize();

    // reset counter for next replay (this replay's entries already written)
    if (fc == 0) g_cnt[t] = 0;

    const __half2 NEGINF = __half2half2(__ushort_as_half(0xFC00));
    __half2 acc[8];                          // [head][lo/hi]
#pragma unroll
    for (int k = 0; k < 8; k++) acc[k] = NEGINF;

    const uint2* np = g_neigh2 + t * DEG;

#pragma unroll
    for (int e = 0; e < 8; e++) {
        uint2 pk = np[e];
        int n0 = pk.x & 0xFFFF;
        int n1 = pk.x >> 16;
        int n2 = pk.y;
        uint2 a0 = g_feat_h[n0 * 16 + fc];
        uint2 a1 = g_feat_h[n1 * 16 + fc];
        uint2 a2 = g_feat_h[n2 * 16 + fc];
        __half2 f0l = *reinterpret_cast<__half2*>(&a0.x);
        __half2 f0h = *reinterpret_cast<__half2*>(&a0.y);
        __half2 f1l = *reinterpret_cast<__half2*>(&a1.x);
        __half2 f1h = *reinterpret_cast<__half2*>(&a1.y);
        __half2 f2l = *reinterpret_cast<__half2*>(&a2.x);
        __half2 f2h = *reinterpret_cast<__half2*>(&a2.y);

#pragma unroll
        for (int h = 0; h < 4; h++) {
            __half2 ml = __hmul2(w2[h * 3 + 0], f0l);
            ml = __hfma2(w2[h * 3 + 1], f1l, ml);
            ml = __hfma2(w2[h * 3 + 2], f2l, ml);
            __half2 mh = __hmul2(w2[h * 3 + 0], f0h);
            mh = __hfma2(w2[h * 3 + 1], f1h, mh);
            mh = __hfma2(w2[h * 3 + 2], f2h, mh);
            acc[h * 2 + 0] = __hmax2(acc[h * 2 + 0], ml);
            acc[h * 2 + 1] = __hmax2(acc[h * 2 + 1], mh);
        }
    }

    // out[t, h*64 + f] -> float4 index t*64 + h*16 + fc
    int ob = t * 64 + fc;
#pragma unroll
    for (int h = 0; h < 4; h++) {
        float2 lo = __half22float2(acc[h * 2 + 0]);
        float2 hi = __half22float2(acc[h * 2 + 1]);
        float x0 = base.x + lo.x;
        float x1 = base.y + lo.y;
        float x2 = base.z + hi.x;
        float x3 = base.w + hi.y;
        out4[ob + h * 16] = make_float4(fmaxf(x0, ALPHA * x0), fmaxf(x1, ALPHA * x1),
                                        fmaxf(x2, ALPHA * x2), fmaxf(x3, ALPHA * x3));
    }
}

// ---------------------------------------------------------------------------
// Launcher: prep on the capture stream, gat launched with the PDL attribute
// so its prologue overlaps prep's tail inside the captured graph.
// ---------------------------------------------------------------------------
extern "C" void kernel_launch(void* const* d_in, const int* in_sizes, int n_in,
                              void* d_out, int out_size) {
    const int*   batch = nullptr;
    const float* feat  = nullptr;
    const float* attw  = nullptr;
    for (int i = 0; i < n_in; i++) {
        if (in_sizes[i] == ENTRIES_TOTAL)              batch = (const int*)d_in[i];
        else if (in_sizes[i] == N_NODES * N_FEAT)      feat  = (const float*)d_in[i];
        else if (in_sizes[i] == N_HEADS * (NTYPE - 1)) attw  = (const float*)d_in[i];
    }

    prep_kernel<<<PREP_BLOCKS, 256>>>(
        reinterpret_cast<const float4*>(feat),
        reinterpret_cast<const int4*>(batch));

    cudaLaunchConfig_t cfg = {};
    cfg.gridDim  = dim3(N_NODES / 16, 1, 1);
    cfg.blockDim = dim3(256, 1, 1);
    cfg.dynamicSmemBytes = 0;
    cfg.stream = 0;   // same (legacy) stream the harness captures
    cudaLaunchAttribute attrs[1];
    attrs[0].id = cudaLaunchAttributeProgrammaticStreamSerialization;
    attrs[0].val.programmaticStreamSerializationAllowed = 1;
    cfg.attrs    = attrs;
    cfg.numAttrs = 1;

    cudaLaunchKernelEx(&cfg, gat_kernel,
                       reinterpret_cast<const float4*>(feat),
                       attw,
                       reinterpret_cast<float4*>(d_out));
}

// round 14
// speedup vs baseline: 1.0462x; 1.0009x over previous
#include <cuda_runtime.h>
#include <cuda_fp16.h>
#include <math.h>

// Problem constants (fixed by the dataset)
#define N_NODES       65536
#define N_FEAT        64
#define N_HEADS       4
#define NTYPE         4
#define BATCH_ROWS    131072
#define ENTRIES_TOTAL (BATCH_ROWS * NTYPE)   // 524288
#define DEG           8                      // each node appears exactly 8 times
#define ALPHA         0.2f

// Scratch (allocation-free rule: __device__ globals; zero-init at module load)
__device__ int   g_cnt[N_NODES];
__device__ uint2 g_neigh2[N_NODES * DEG];     // packed: x = n0 | n1<<16, y = n2
__device__ uint2 g_feat_h[N_NODES * 16];      // fp16 feature table, 4 halfs per uint2

#define PREP_BLOCKS  1024                     // single wave; 262,144 threads
#define PREP_STRIDE  (PREP_BLOCKS * 256)

// ---------------------------------------------------------------------------
// Kernel 1: fused prep, SINGLE WAVE, early PDL trigger.
//   Each thread: 2 scatter entries + 2 uint4 fp16-converts (4 float4 loads).
//   cudaTriggerProgrammaticLaunchCompletion() at block entry lets the
//   dependent gat kernel launch (ramp + pre-sync loads) while prep runs.
// g_cnt must be all-zero on entry (static zero-init; gat_kernel re-zeros).
// ---------------------------------------------------------------------------
__device__ __forceinline__ void scatter_one(int idx, const int4* __restrict__ batch4) {
    int r = idx >> 2;                  // batch row
    int i = idx & 3;                   // filter / position of target
    int4 b = batch4[r];
    int tgt = (i == 0) ? b.x : (i == 1) ? b.y : (i == 2) ? b.z : b.w;
    // cols[i] = all j != i, in order (maps directly to att weight column)
    unsigned n0 = (i == 0) ? b.y : b.x;
    unsigned n1 = (i <= 1) ? b.z : b.y;
    unsigned n2 = (i == 3) ? b.z : b.w;
    int p = atomicAdd(&g_cnt[tgt], 1);
    g_neigh2[tgt * DEG + p] = make_uint2(n0 | (n1 << 16), n2);
}

__device__ __forceinline__ void conv_one(int i, const float4* __restrict__ feat4) {
    float4 v0 = feat4[i * 2 + 0];
    float4 v1 = feat4[i * 2 + 1];
    __half2 h0 = __floats2half2_rn(v0.x, v0.y);
    __half2 h1 = __floats2half2_rn(v0.z, v0.w);
    __half2 h2 = __floats2half2_rn(v1.x, v1.y);
    __half2 h3 = __floats2half2_rn(v1.z, v1.w);
    uint4 u;
    u.x = *reinterpret_cast<unsigned int*>(&h0);
    u.y = *reinterpret_cast<unsigned int*>(&h1);
    u.z = *reinterpret_cast<unsigned int*>(&h2);
    u.w = *reinterpret_cast<unsigned int*>(&h3);
    reinterpret_cast<uint4*>(g_feat_h)[i] = u;
}

__global__ void __launch_bounds__(256) prep_kernel(const float4* __restrict__ feat4,
                                                   const int4*   __restrict__ batch4) {
    // Early trigger: every block is scheduled (single wave), so the dependent
    // kernel may begin launching immediately and overlap all of prep.
    if (threadIdx.x == 0) cudaTriggerProgrammaticLaunchCompletion();

    int idx = blockIdx.x * 256 + threadIdx.x;      // [0, 262144)

    conv_one(idx,               feat4);
    conv_one(idx + PREP_STRIDE, feat4);
    scatter_one(idx,               batch4);
    scatter_one(idx + PREP_STRIDE, batch4);
}

// ---------------------------------------------------------------------------
// Kernel 2: per-node reduction (atomic-free), fp16 gathers + HFMA2 math.
//   PDL: the prologue (weights + fp32 base loads, pure-input data) runs
//   BEFORE cudaGridDependencySynchronize(); everything touching prep outputs
//   (g_neigh2, g_feat_h, g_cnt reset) runs after.
//   16 threads/node; gathers are LDG.64 (16 lanes = one 128B line per row).
// ---------------------------------------------------------------------------
__global__ void __launch_bounds__(256, 4) gat_kernel(
    const float4* __restrict__ feat4,    // [N_NODES*16] fp32 (for base)
    const float*  __restrict__ attw,     // [4 heads][3 positions]
    float4*       __restrict__ out4)     // [N_NODES*64]
{
    int tid = threadIdx.x;
    int t   = blockIdx.x * 16 + (tid >> 4);  // node
    int fc  = tid & 15;                      // half2-pair chunk of the row

    // ---- prep-independent prologue (overlaps the prep kernel via PDL) ----
    __half2 w2[12];
#pragma unroll
    for (int k = 0; k < 12; k++) {
        float w = __ldg(attw + k);
        w2[k] = __float2half2_rn(w);
    }
    const float4 base = feat4[t * 16 + fc];

    // ---- wait for prep_kernel completion ----
    cudaGridDependencySynchronize();

    // reset counter for next replay (this replay's entries already written)
    if (fc == 0) g_cnt[t] = 0;

    const __half2 NEGINF = __half2half2(__ushort_as_half(0xFC00));
    __half2 acc[8];                          // [head][lo/hi]
#pragma unroll
    for (int k = 0; k < 8; k++) acc[k] = NEGINF;

    const uint2* np = g_neigh2 + t * DEG;

#pragma unroll
    for (int e = 0; e < 8; e++) {
        uint2 pk = np[e];
        int n0 = pk.x & 0xFFFF;
        int n1 = pk.x >> 16;
        int n2 = pk.y;
        uint2 a0 = g_feat_h[n0 * 16 + fc];
        uint2 a1 = g_feat_h[n1 * 16 + fc];
        uint2 a2 = g_feat_h[n2 * 16 + fc];
        __half2 f0l = *reinterpret_cast<__half2*>(&a0.x);
        __half2 f0h = *reinterpret_cast<__half2*>(&a0.y);
        __half2 f1l = *reinterpret_cast<__half2*>(&a1.x);
        __half2 f1h = *reinterpret_cast<__half2*>(&a1.y);
        __half2 f2l = *reinterpret_cast<__half2*>(&a2.x);
        __half2 f2h = *reinterpret_cast<__half2*>(&a2.y);

#pragma unroll
        for (int h = 0; h < 4; h++) {
            __half2 ml = __hmul2(w2[h * 3 + 0], f0l);
            ml = __hfma2(w2[h * 3 + 1], f1l, ml);
            ml = __hfma2(w2[h * 3 + 2], f2l, ml);
            __half2 mh = __hmul2(w2[h * 3 + 0], f0h);
            mh = __hfma2(w2[h * 3 + 1], f1h, mh);
            mh = __hfma2(w2[h * 3 + 2], f2h, mh);
            acc[h * 2 + 0] = __hmax2(acc[h * 2 + 0], ml);
            acc[h * 2 + 1] = __hmax2(acc[h * 2 + 1], mh);
        }
    }

    // out[t, h*64 + f] -> float4 index t*64 + h*16 + fc
    int ob = t * 64 + fc;
#pragma unroll
    for (int h = 0; h < 4; h++) {
        float2 lo = __half22float2(acc[h * 2 + 0]);
        float2 hi = __half22float2(acc[h * 2 + 1]);
        float x0 = base.x + lo.x;
        float x1 = base.y + lo.y;
        float x2 = base.z + hi.x;
        float x3 = base.w + hi.y;
        out4[ob + h * 16] = make_float4(fmaxf(x0, ALPHA * x0), fmaxf(x1, ALPHA * x1),
                                        fmaxf(x2, ALPHA * x2), fmaxf(x3, ALPHA * x3));
    }
}

// ---------------------------------------------------------------------------
// Launcher: prep (early-trigger) on the capture stream, gat launched with the
// PDL attribute so its ramp + prologue overlap prep inside the captured graph.
// ---------------------------------------------------------------------------
extern "C" void kernel_launch(void* const* d_in, const int* in_sizes, int n_in,
                              void* d_out, int out_size) {
    const int*   batch = nullptr;
    const float* feat  = nullptr;
    const float* attw  = nullptr;
    for (int i = 0; i < n_in; i++) {
        if (in_sizes[i] == ENTRIES_TOTAL)              batch = (const int*)d_in[i];
        else if (in_sizes[i] == N_NODES * N_FEAT)      feat  = (const float*)d_in[i];
        else if (in_sizes[i] == N_HEADS * (NTYPE - 1)) attw  = (const float*)d_in[i];
    }

    prep_kernel<<<PREP_BLOCKS, 256>>>(
        reinterpret_cast<const float4*>(feat),
        reinterpret_cast<const int4*>(batch));

    cudaLaunchConfig_t cfg = {};
    cfg.gridDim  = dim3(N_NODES / 16, 1, 1);
    cfg.blockDim = dim3(256, 1, 1);
    cfg.dynamicSmemBytes = 0;
    cfg.stream = 0;   // same (legacy) stream the harness captures
    cudaLaunchAttribute attrs[1];
    attrs[0].id = cudaLaunchAttributeProgrammaticStreamSerialization;
    attrs[0].val.programmaticStreamSerializationAllowed = 1;
    cfg.attrs    = attrs;
    cfg.numAttrs = 1;

    cudaLaunchKernelEx(&cfg, gat_kernel,
                       reinterpret_cast<const float4*>(feat),
                       attw,
                       reinterpret_cast<float4*>(d_out));
}